// round 8
// baseline (speedup 1.0000x reference)
#include <cuda_runtime.h>
#include <cstdint>

#define BQ 32
#define DK 128
#define KTOP 10
#define TILE_R 128
#define KC 32
#define NCHUNK (DK / KC)          // 4
#define STAGES 4                  // ring slots == chunks per tile
#define CHUNK (TILE_R * KC)       // floats per chunk buffer (16 KB)
#define THREADS 256
#define NB1 296                   // stage-1 grid: 2 CTAs per SM

// ---------------- device scratch (no allocations allowed) ----------------
__device__ float g_cand_val[NB1 * BQ * KTOP];
__device__ int   g_cand_idx[NB1 * BQ * KTOP];
__device__ float g_dummy;

// ---------------- helpers ----------------
__device__ __forceinline__ void fma2(unsigned long long& acc,
                                     unsigned long long a,
                                     unsigned long long b) {
    asm("fma.rn.f32x2 %0, %1, %2, %0;" : "+l"(acc) : "l"(a), "l"(b));
}
__device__ __forceinline__ float lo32(unsigned long long v) {
    return __uint_as_float((unsigned)(v & 0xffffffffull));
}
__device__ __forceinline__ float hi32(unsigned long long v) {
    return __uint_as_float((unsigned)(v >> 32));
}
__device__ __forceinline__ void cp_async16(unsigned smem_addr, const void* gptr, bool valid) {
    int sz = valid ? 16 : 0;   // src-size 0 -> zero-fill destination
    asm volatile("cp.async.cg.shared.global [%0], [%1], 16, %2;"
                 :: "r"(smem_addr), "l"(gptr), "r"(sz));
}
__device__ __forceinline__ void cp_commit() {
    asm volatile("cp.async.commit_group;");
}
template <int N>
__device__ __forceinline__ void cp_wait() {
    asm volatile("cp.async.wait_group %0;" :: "n"(N));
}

// better(a, b): larger value wins; ties -> smaller index (matches lax.top_k)
__device__ __forceinline__ bool better(float av, int ai, float bv, int bi) {
    return (av > bv) || (av == bv && ai < bi);
}

// ---------------- stage 1 ----------------
// Corpus smem chunk buffer: TILE_R rows x KC floats, row stride KC. Each row's
// eight 16B quads XOR-swizzled by (row & 7): 16B-aligned cp.async dsts AND
// conflict-free LDS.128 reads.
__device__ __forceinline__ void stage_chunk(const float* __restrict__ corpus, int N,
                                            int row0, int c, float* buf) {
    int tid = threadIdx.x;
    unsigned sbase = (unsigned)__cvta_generic_to_shared(buf);
    #pragma unroll
    for (int s = 0; s < (TILE_R * KC / 4) / THREADS; ++s) {   // 4 iters
        int idx = tid + s * THREADS;
        int r = idx >> 3, kq = idx & 7;
        bool valid = (row0 + r) < N;
        const float* g = corpus + (valid ? ((size_t)(row0 + r) * DK + c * KC + kq * 4) : 0);
        unsigned d = sbase + (unsigned)(r * KC + ((kq ^ (r & 7)) << 2)) * 4u;
        cp_async16(d, g, valid);
    }
}

__device__ __forceinline__ void insert_locked(float* tv, int* ti, int* lck,
                                              int q, float v, int gi) {
    float* L = tv + q * KTOP;
    int*   I = ti + q * KTOP;
    while (atomicCAS(&lck[q], 0, 1) != 0) { __nanosleep(32); }
    __threadfence_block();
    if (better(v, gi, L[KTOP - 1], I[KTOP - 1])) {
        int p = KTOP - 1;
        while (p > 0 && better(v, gi, L[p - 1], I[p - 1])) {
            L[p] = L[p - 1]; I[p] = I[p - 1]; --p;
        }
        L[p] = v; I[p] = gi;
    }
    __threadfence_block();
    atomicExch(&lck[q], 0);
}

__global__ void __launch_bounds__(THREADS, 2)
stage1_kernel(const float* __restrict__ query, const float* __restrict__ corpus, int N) {
    extern __shared__ float smem[];
    float* cbuf = smem;                                 // STAGES*CHUNK
    float* qs   = cbuf + STAGES * CHUNK;                // BQ*DK (normalized queries)
    float* rns  = qs + BQ * DK;                         // TILE_R
    float* tv   = rns + TILE_R;                         // BQ*KTOP
    int*   ti   = (int*)(tv + BQ * KTOP);               // BQ*KTOP
    int*   lck  = ti + BQ * KTOP;                       // BQ

    const int tid  = threadIdx.x;
    const int w    = tid >> 5;            // 0..7
    const int lane = tid & 31;
    const int qg   = w & 3;               // query group: queries qg*8 .. qg*8+7
    const int rq   = w >> 2;              // 0..1
    const int row0l = lane + 64 * rq;     // first row this thread handles
    const int row1l = row0l + 32;         // second row

    // --- init top-k state (full 320 entries) + fused query normalization ---
    for (int i = tid; i < BQ * KTOP; i += THREADS) { tv[i] = -INFINITY; ti[i] = 0x7fffffff; }
    if (tid < BQ) lck[tid] = 0;
    for (int row = w; row < BQ; row += 8) {
        float4 v = reinterpret_cast<const float4*>(query + row * DK)[lane];
        float s = v.x * v.x + v.y * v.y + v.z * v.z + v.w * v.w;
        #pragma unroll
        for (int off = 16; off; off >>= 1) s += __shfl_xor_sync(0xffffffffu, s, off);
        float rn = rsqrtf(s + 1e-12f);
        float4 o = make_float4(v.x * rn, v.y * rn, v.z * rn, v.w * rn);
        reinterpret_cast<float4*>(qs + row * DK)[lane] = o;
    }

    const int ntiles = (N + TILE_R - 1) / TILE_R;
    const int bid = blockIdx.x;
    const int my_tiles = (bid < ntiles) ? ((ntiles - 1 - bid) / NB1 + 1) : 0;
    const int total_s = my_tiles * NCHUNK;

    // prologue: prefetch chunk stream 0,1,2 (one group each)
    #pragma unroll
    for (int s = 0; s < STAGES - 1; ++s) {
        if (s < total_s)
            stage_chunk(corpus, N, (bid + (s >> 2) * NB1) * TILE_R, s & 3,
                        cbuf + (s & 3) * CHUNK);
        cp_commit();
    }
    __syncthreads();   // qs/topk init visible

    for (int tl = 0; tl < my_tiles; ++tl) {
        const int row0 = (bid + tl * NB1) * TILE_R;

        unsigned long long acc0[8], acc1[8], ss0, ss1;
        #pragma unroll
        for (int j = 0; j < 8; ++j) { acc0[j] = 0ull; acc1[j] = 0ull; }
        ss0 = ss1 = 0ull;

        #pragma unroll
        for (int c = 0; c < NCHUNK; ++c) {
            const int s = tl * NCHUNK + c;
            cp_wait<STAGES - 2>();     // chunk s resident
            __syncthreads();           // all warps done with slot (s-1)%4; data visible
            const int sp = s + STAGES - 1;
            if (sp < total_s)
                stage_chunk(corpus, N, (bid + (sp >> 2) * NB1) * TILE_R, sp & 3,
                            cbuf + (sp & 3) * CHUNK);
            cp_commit();

            const float* buf = cbuf + c * CHUNK;
            const float* qb  = qs + (qg * 8) * DK + c * KC;
            #pragma unroll
            for (int kkc = 0; kkc < 8; ++kkc) {           // 4 k per step
                const float* cp0 = buf + row0l * KC + ((kkc ^ (row0l & 7)) << 2);
                const float* cp1 = buf + row1l * KC + ((kkc ^ (row1l & 7)) << 2);
                ulonglong2 cv0 = *reinterpret_cast<const ulonglong2*>(cp0);
                ulonglong2 cv1 = *reinterpret_cast<const ulonglong2*>(cp1);
                unsigned long long qx[8], qy[8];
                #pragma unroll
                for (int j = 0; j < 8; ++j) {
                    ulonglong2 v = *reinterpret_cast<const ulonglong2*>(qb + j * DK + kkc * 4);
                    qx[j] = v.x; qy[j] = v.y;
                }
                if (qg == 0) {
                    fma2(ss0, cv0.x, cv0.x); fma2(ss0, cv0.y, cv0.y);
                    fma2(ss1, cv1.x, cv1.x); fma2(ss1, cv1.y, cv1.y);
                }
                #pragma unroll
                for (int j = 0; j < 8; ++j) {
                    fma2(acc0[j], cv0.x, qx[j]); fma2(acc0[j], cv0.y, qy[j]);
                    fma2(acc1[j], cv1.x, qx[j]); fma2(acc1[j], cv1.y, qy[j]);
                }
            }
        }

        // row inverse norms (qg==0 warps w0/w4 cover all 128 rows)
        if (qg == 0) {
            rns[row0l] = rsqrtf(lo32(ss0) + hi32(ss0) + 1e-12f);
            rns[row1l] = rsqrtf(lo32(ss1) + hi32(ss1) + 1e-12f);
        }
        __syncthreads();

        // scores + block top-k
        {
            int gr0 = row0 + row0l, gr1 = row0 + row1l;
            float rn0 = rns[row0l], rn1 = rns[row1l];
            if (gr0 < N) {
                #pragma unroll
                for (int j = 0; j < 8; ++j) {
                    float v = (lo32(acc0[j]) + hi32(acc0[j])) * rn0;
                    int q = qg * 8 + j;
                    if (v > tv[q * KTOP + KTOP - 1]) insert_locked(tv, ti, lck, q, v, gr0);
                }
            }
            if (gr1 < N) {
                #pragma unroll
                for (int j = 0; j < 8; ++j) {
                    float v = (lo32(acc1[j]) + hi32(acc1[j])) * rn1;
                    int q = qg * 8 + j;
                    if (v > tv[q * KTOP + KTOP - 1]) insert_locked(tv, ti, lck, q, v, gr1);
                }
            }
        }
        // no trailing sync needed: next chunk-top sync orders topk vs rns rewrite
    }

    __syncthreads();
    for (int c = tid; c < BQ * KTOP; c += THREADS) {
        g_cand_val[blockIdx.x * BQ * KTOP + c] = tv[c];
        g_cand_idx[blockIdx.x * BQ * KTOP + c] = ti[c];
    }
}

// ---------------- stage 2: merge candidates, write outputs ----------------
__global__ void __launch_bounds__(256)
finalize_kernel(const float* __restrict__ corpus, float* __restrict__ out,
                int N, int nb) {
    const int q = blockIdx.x;
    const int tid = threadIdx.x;
    __shared__ float sv[256 * KTOP];
    __shared__ int   si[256 * KTOP];
    __shared__ float wbv[8]; __shared__ int wbi[8]; __shared__ int wbp[8];
    __shared__ float selv[KTOP]; __shared__ int seli[KTOP];
    __shared__ float rsel[KTOP];

    float lv[KTOP]; int li[KTOP];
    #pragma unroll
    for (int k = 0; k < KTOP; ++k) { lv[k] = -INFINITY; li[k] = 0x7fffffff; }

    int total = nb * KTOP;
    for (int c = tid; c < total; c += 256) {
        int blk = c / KTOP, k = c % KTOP;
        float v = g_cand_val[blk * (BQ * KTOP) + q * KTOP + k];
        int  ix = g_cand_idx[blk * (BQ * KTOP) + q * KTOP + k];
        if (better(v, ix, lv[KTOP - 1], li[KTOP - 1])) {
            int p = KTOP - 1;
            while (p > 0 && better(v, ix, lv[p - 1], li[p - 1])) {
                lv[p] = lv[p - 1]; li[p] = li[p - 1]; --p;
            }
            lv[p] = v; li[p] = ix;
        }
    }
    #pragma unroll
    for (int k = 0; k < KTOP; ++k) { sv[tid * KTOP + k] = lv[k]; si[tid * KTOP + k] = li[k]; }
    __syncthreads();

    const int w = tid >> 5, l = tid & 31;
    for (int r = 0; r < KTOP; ++r) {
        float bv = -INFINITY; int bi = 0x7fffffff; int bp = -1;
        for (int c = tid; c < 256 * KTOP; c += 256) {
            float v = sv[c]; int ix = si[c];
            if (bp < 0 || better(v, ix, bv, bi)) { bv = v; bi = ix; bp = c; }
        }
        #pragma unroll
        for (int off = 16; off; off >>= 1) {
            float ov = __shfl_xor_sync(0xffffffffu, bv, off);
            int oi = __shfl_xor_sync(0xffffffffu, bi, off);
            int op = __shfl_xor_sync(0xffffffffu, bp, off);
            if (op >= 0 && (bp < 0 || better(ov, oi, bv, bi))) { bv = ov; bi = oi; bp = op; }
        }
        if (l == 0) { wbv[w] = bv; wbi[w] = bi; wbp[w] = bp; }
        __syncthreads();
        if (tid == 0) {
            float fv = wbv[0]; int fi = wbi[0]; int fp = wbp[0];
            for (int ww = 1; ww < 8; ++ww)
                if (wbp[ww] >= 0 && (fp < 0 || better(wbv[ww], wbi[ww], fv, fi))) {
                    fv = wbv[ww]; fi = wbi[ww]; fp = wbp[ww];
                }
            selv[r] = fv; seli[r] = (fi == 0x7fffffff) ? 0 : fi;
            if (fp >= 0) sv[fp] = -INFINITY;
        }
        __syncthreads();
    }

    if (tid < KTOP) {
        out[q * KTOP + tid] = selv[tid];
        out[BQ * KTOP + q * KTOP + tid] = (float)seli[tid];
    }

    // recompute inverse norms for the 10 selected rows
    for (int r = w; r < KTOP; r += 8) {
        int row = seli[r]; if (row < 0 || row >= N) row = 0;
        float4 v = reinterpret_cast<const float4*>(corpus + (size_t)row * DK)[l];
        float s = v.x * v.x + v.y * v.y + v.z * v.z + v.w * v.w;
        #pragma unroll
        for (int off = 16; off; off >>= 1) s += __shfl_xor_sync(0xffffffffu, s, off);
        if (l == 0) rsel[r] = rsqrtf(s + 1e-12f);
    }
    __syncthreads();

    size_t base = (size_t)BQ * KTOP * 2 + (size_t)q * KTOP * DK;
    for (int e = tid; e < KTOP * DK; e += 256) {
        int r = e / DK, d = e % DK;
        int row = seli[r]; if (row < 0 || row >= N) row = 0;
        out[base + e] = corpus[(size_t)row * DK + d] * rsel[r];
    }
}

// keeps the per-replay launch count at 3 so ncu -s 5 lands on stage1
__global__ void dummy_kernel() { g_dummy = g_cand_val[0]; }

// ---------------- launch ----------------
extern "C" void kernel_launch(void* const* d_in, const int* in_sizes, int n_in,
                              void* d_out, int out_size) {
    const float* query  = (const float*)d_in[0];
    const float* corpus = (const float*)d_in[1];
    const int N = in_sizes[1] / DK;

    const int smem_bytes =
        (STAGES * CHUNK + BQ * DK + TILE_R + BQ * KTOP) * 4 +
        (BQ * KTOP + BQ) * 4;
    cudaFuncSetAttribute(stage1_kernel,
                         cudaFuncAttributeMaxDynamicSharedMemorySize, smem_bytes);

    stage1_kernel<<<NB1, THREADS, smem_bytes>>>(query, corpus, N);
    finalize_kernel<<<BQ, 256>>>(corpus, (float*)d_out, N, NB1);
    dummy_kernel<<<1, 1>>>();
}